// round 16
// baseline (speedup 1.0000x reference)
#include <cuda_runtime.h>
#include <cuda_bf16.h>
#include <cuda_fp16.h>
#include <cstdint>

// ---------------------------------------------------------------------------
// BasicDMPNN on GB300 — round 16: spill-free MLP-16 fused gather+update.
//   * warp gathers its 16 nodes via uniform-bound predicated loop (all state
//     in registers; r14's local-memory spill eliminated)
//   * ping-pong fp16 message buffers (r11 correctness scheme)
//   * g_agg round-trip deleted; parallel CSR scan; piggybacked zero fills
//   * GEMM pipeline = r12/13 winner (bf16x3 mma.sync, register-resident h)
// ---------------------------------------------------------------------------

#define NMAX 50000
#define EMAX 800000
#define MMAX 2000
#define NTAB 476

__device__ __align__(16) float g_bias[NTAB * 128];      // ab@Wu1[:192]+bu1
__device__ __align__(16) __half g_msgInit[NTAB * 128];  // relu(ab@Wi+bi), fp16
__device__ __align__(16) __half g_msgT0[NMAX * 4 * 128];
__device__ __align__(16) __half g_msgT1[NMAX * 4 * 128];
__device__ __align__(16) float g_mol[MMAX * 128];
__device__ __align__(16) uint4 g_Wf1[4096];             // Wu1agg frag image (hi/lo)
__device__ __align__(16) uint4 g_Wf2[4096];             // Wu2 frag image (hi/lo)

// CSR scratch
__device__ int g_hist[NMAX];
__device__ int g_rowStart[NMAX + 1];
__device__ int g_cursor[NMAX];
__device__ int g_blockSum[256];
__device__ int g_blockOff[256];
__device__ int g_row0[EMAX];   // x[src]*4+attr
__device__ int g_rowU[EMAX];   // src*4+attr

// ---------------------------------------------------------------------------
__device__ __forceinline__ uint32_t pack_bf16x2(float e0, float e1) {
    __nv_bfloat162 p = __floats2bfloat162_rn(e0, e1);
    return *reinterpret_cast<uint32_t*>(&p);
}
__device__ __forceinline__ void split2(float e0, float e1,
                                       uint32_t& hi, uint32_t& lo) {
    float h0 = __bfloat162float(__float2bfloat16(e0));
    float h1 = __bfloat162float(__float2bfloat16(e1));
    hi = pack_bf16x2(h0, h1);
    lo = pack_bf16x2(e0 - h0, e1 - h1);
}
__device__ __forceinline__ void mma_bf16(float d[4], const uint32_t a[4],
                                         uint32_t b0, uint32_t b1) {
    asm volatile(
        "mma.sync.aligned.m16n8k16.row.col.f32.bf16.bf16.f32 "
        "{%0,%1,%2,%3}, {%4,%5,%6,%7}, {%8,%9}, {%0,%1,%2,%3};"
        : "+f"(d[0]), "+f"(d[1]), "+f"(d[2]), "+f"(d[3])
        : "r"(a[0]), "r"(a[1]), "r"(a[2]), "r"(a[3]), "r"(b0), "r"(b1));
}
// swizzled index into a 16-row x 64-word per-warp staging tile
__device__ __forceinline__ int aw(int row, int kk) {
    return row * 64 + (kk ^ ((row & 7) << 2));
}
__device__ __forceinline__ void acc_row(float4& acc, const __half* __restrict__ table,
                                        int r, int lane) {
    uint2 u = ((const uint2*)(table + (size_t)r * 128))[lane];
    __half2 p0 = *reinterpret_cast<__half2*>(&u.x);
    __half2 p1 = *reinterpret_cast<__half2*>(&u.y);
    float2 f0 = __half22float2(p0);
    float2 f1 = __half22float2(p1);
    acc.x += f0.x; acc.y += f0.y; acc.z += f1.x; acc.w += f1.y;
}

// Block-wide (256 threads) exclusive scan of one int per thread.
__device__ __forceinline__ int block_scan_ex(int v, int tid) {
    int lane = tid & 31;
    int wid = tid >> 5;
    int inc = v;
#pragma unroll
    for (int o = 1; o < 32; o <<= 1) {
        int t = __shfl_up_sync(0xffffffffu, inc, o);
        if (lane >= o) inc += t;
    }
    __shared__ int wsum[8], woff[8];
    if (lane == 31) wsum[wid] = inc;
    __syncthreads();
    if (tid == 0) {
        int run = 0;
#pragma unroll
        for (int k = 0; k < 8; k++) { woff[k] = run; run += wsum[k]; }
    }
    __syncthreads();
    return woff[wid] + inc - v;
}

// ---------------------------------------------------------------------------
// CSR build: count -> 3-phase parallel scan -> fill
// ---------------------------------------------------------------------------
__global__ void csr_count_kernel(const int* __restrict__ dst, int E) {
    for (int e = blockIdx.x * blockDim.x + threadIdx.x; e < E;
         e += gridDim.x * blockDim.x)
        atomicAdd(&g_hist[dst[e]], 1);
}
__global__ void csr_scan1_kernel(int N) {
    int i = blockIdx.x * 256 + threadIdx.x;
    int v = (i < N) ? g_hist[i] : 0;
    int ex = block_scan_ex(v, threadIdx.x);
    if (i < N) g_rowStart[i] = ex;
    if (threadIdx.x == 255) g_blockSum[blockIdx.x] = ex + v;
}
__global__ void csr_scan2_kernel(int B, int N) {
    int tid = threadIdx.x;
    int v = (tid < B) ? g_blockSum[tid] : 0;
    int ex = block_scan_ex(v, tid);
    if (tid < B) g_blockOff[tid] = ex;
    if (tid == B - 1) g_rowStart[N] = ex + v;
}
__global__ void csr_scan3_kernel(int N) {
    int i = blockIdx.x * 256 + threadIdx.x;
    if (i < N) {
        int val = g_rowStart[i] + g_blockOff[blockIdx.x];
        g_rowStart[i] = val;
        g_cursor[i] = val;
    }
}
__global__ void csr_fill_kernel(const int* __restrict__ src,
                                const int* __restrict__ dst,
                                const int* __restrict__ attr,
                                const int* __restrict__ x, int E) {
    for (int e = blockIdx.x * blockDim.x + threadIdx.x; e < E;
         e += gridDim.x * blockDim.x) {
        int d = dst[e];
        int s = src[e];
        int a = attr[e];
        int pos = atomicAdd(&g_cursor[d], 1);
        g_rowU[pos] = s * 4 + a;
        g_row0[pos] = x[s] * 4 + a;
    }
}

// ---------------------------------------------------------------------------
// Final molecule pooling: gather node_state from g_msgT1 (pass-3 output)
// and red.add into g_mol[batch[n]].
__global__ void gather_mol_kernel(const int* __restrict__ batch, int N) {
    int lane = threadIdx.x & 31;
    int w = (blockIdx.x * blockDim.x + threadIdx.x) >> 5;
    int nw = (gridDim.x * blockDim.x) >> 5;
    for (int n = w; n < N; n += nw) {
        int s0 = g_rowStart[n];
        int s1 = g_rowStart[n + 1];
        float4 acc = make_float4(0.f, 0.f, 0.f, 0.f);
        int j = s0;
        for (; j + 2 <= s1; j += 2) {
            int r0 = __ldg(g_rowU + j);
            int r1 = __ldg(g_rowU + j + 1);
            acc_row(acc, g_msgT1, r0, lane);
            acc_row(acc, g_msgT1, r1, lane);
        }
        if (j < s1) acc_row(acc, g_msgT1, __ldg(g_rowU + j), lane);
        float* outp = g_mol + (size_t)__ldg(batch + n) * 128 + lane * 4;
        asm volatile("red.global.add.v4.f32 [%0], {%1,%2,%3,%4};"
                     :: "l"(outp), "f"(acc.x), "f"(acc.y), "f"(acc.z), "f"(acc.w)
                     : "memory");
    }
}

// ---------------------------------------------------------------------------
// Build the two 476x128 tables (fp32 math; msgInit stored fp16).
// Piggyback: zero g_hist.
__global__ void table_kernel(const float* __restrict__ atom_table,
                             const float* __restrict__ bond_table,
                             const float* __restrict__ Wi,
                             const float* __restrict__ bi,
                             const float* __restrict__ Wu1,
                             const float* __restrict__ bu1, int N) {
    int t = blockIdx.x >> 2;
    int a = blockIdx.x & 3;
    int j = threadIdx.x;

    for (int i = blockIdx.x * 128 + j; i < N; i += NTAB * 128) g_hist[i] = 0;

    __shared__ float sAtom[128];
    __shared__ float sBond[64];
    sAtom[j] = atom_table[t * 128 + j];
    if (j < 64) sBond[j] = bond_table[a * 64 + j];
    __syncthreads();

    float accI = bi[j];
    float accB = bu1[j];
#pragma unroll 8
    for (int k = 0; k < 128; k++) {
        float av = sAtom[k];
        accI = fmaf(av, Wi[k * 128 + j], accI);
        accB = fmaf(av, Wu1[k * 128 + j], accB);
    }
#pragma unroll 8
    for (int k = 0; k < 64; k++) {
        float bv = sBond[k];
        accI = fmaf(bv, Wi[(128 + k) * 128 + j], accI);
        accB = fmaf(bv, Wu1[(128 + k) * 128 + j], accB);
    }
    g_msgInit[blockIdx.x * 128 + j] = __float2half_rn(fmaxf(accI, 0.f));
    g_bias[blockIdx.x * 128 + j] = accB;
}

// ---------------------------------------------------------------------------
// Pack W (k-major [128,128]) into fragment-ordered bf16 hi/lo images.
// Piggyback: zero g_mol.
__global__ void prep_wfrag_kernel(const float* __restrict__ W1,
                                  const float* __restrict__ W2) {
    int i = blockIdx.x * blockDim.x + threadIdx.x;
    {
        float4 z = make_float4(0.f, 0.f, 0.f, 0.f);
        float4* p = (float4*)g_mol;
        for (int q = i; q < MMAX * 32; q += 4096) p[q] = z;
    }
    if (i >= 4096) return;
    int lane = i & 31;
    int ntile = (i >> 5) & 15;
    int ks = i >> 9;
    int k0 = ks * 16 + (lane & 3) * 2;
    int n = ntile * 8 + (lane >> 2);

    const float* Ws[2] = {W1, W2};
    uint4* imgs[2] = {g_Wf1, g_Wf2};
#pragma unroll
    for (int m = 0; m < 2; m++) {
        const float* W = Ws[m];
        uint4 v;
        split2(W[k0 * 128 + n], W[(k0 + 1) * 128 + n], v.x, v.z);
        split2(W[(k0 + 8) * 128 + n], W[(k0 + 9) * 128 + n], v.y, v.w);
        imgs[m][i] = v;
    }
}

// ---------------------------------------------------------------------------
// Fused gather+update pass: 64 nodes/block, 128 threads (4 warps x 16 nodes),
// 2 blocks/SM. smem: staging 32KB + sW 64KB = 96KB.
// pass0: gather from fp16 init table; else from the PREVIOUS msg buffer.
// cur: buffer written this pass (0 -> T0, 1 -> T1).
#define SM_UPD (16384 + 16384 + 65536)

__global__ void __launch_bounds__(128, 2)
fused_update_kernel(int pass0, int cur, const int* __restrict__ x,
                    const float* __restrict__ bu2, int N) {
    extern __shared__ uint32_t smem[];
    uint4* sW = (uint4*)(smem + 8192);     // 4096 uint4 (64KB), W1 then W2

    const int* __restrict__ rowids = pass0 ? g_row0 : g_rowU;
    const __half* __restrict__ table =
        pass0 ? g_msgInit : (cur ? g_msgT0 : g_msgT1);
    __half* __restrict__ msgOut = cur ? g_msgT1 : g_msgT0;

    int tid = threadIdx.x;
    int lane = tid & 31;
    int w = tid >> 5;                      // warp 0..3, owns rows w*16..+15
    int nb = blockIdx.x * 64;
    uint32_t* sAhi = smem + w * 1024;      // warp-private 16x64 staging
    uint32_t* sAlo = smem + 4096 + w * 1024;

    // Phase 0a: W1 -> smem (cooperative)
#pragma unroll
    for (int i = tid; i < 4096; i += 128) sW[i] = g_Wf1[i];

    // Phase 0b: spill-free MLP-16 gather. All arrays indexed ONLY by unroll
    // constants -> registers. Uniform loop bound + predicated loads.
    {
        float4 acc[16];
        int start[16], deg[16];
#pragma unroll
        for (int r = 0; r < 16; r++) {
            int n = nb + w * 16 + r;
            bool v = (n < N);
            int s0 = v ? g_rowStart[n] : 0;
            int s1 = v ? g_rowStart[n + 1] : 0;
            start[r] = s0;
            deg[r] = s1 - s0;
            acc[r] = make_float4(0.f, 0.f, 0.f, 0.f);
        }
        int maxdeg = 0;
#pragma unroll
        for (int r = 0; r < 16; r++) maxdeg = max(maxdeg, deg[r]);

        for (int e = 0; e < maxdeg; e++) {
#pragma unroll
            for (int r = 0; r < 16; r++) {
                if (e < deg[r]) {
                    int row = __ldg(rowids + start[r] + e);
                    acc_row(acc[r], table, row, lane);
                }
            }
        }
        // split -> staging
#pragma unroll
        for (int r = 0; r < 16; r++) {
            uint32_t h0, l0, h1, l1;
            split2(acc[r].x, acc[r].y, h0, l0);
            split2(acc[r].z, acc[r].w, h1, l1);
            int p = aw(r, 2 * lane);
            sAhi[p] = h0; sAhi[p + 1] = h1;
            sAlo[p] = l0; sAlo[p + 1] = l1;
        }
    }
    __syncthreads();

    // GEMM1: D1 = agg @ Wu1agg — warp computes its 16 rows x ALL 128 cols.
    float D1[16][4];
#pragma unroll
    for (int nt = 0; nt < 16; nt++)
#pragma unroll
        for (int q = 0; q < 4; q++) D1[nt][q] = 0.f;

#pragma unroll
    for (int ks = 0; ks < 8; ks++) {
        int lr = lane >> 2;
        int kk = ks * 8 + (lane & 3);
        uint32_t Ahi[4], Alo[4];
        Ahi[0] = sAhi[aw(lr, kk)];
        Ahi[1] = sAhi[aw(lr + 8, kk)];
        Ahi[2] = sAhi[aw(lr, kk + 4)];
        Ahi[3] = sAhi[aw(lr + 8, kk + 4)];
        Alo[0] = sAlo[aw(lr, kk)];
        Alo[1] = sAlo[aw(lr + 8, kk)];
        Alo[2] = sAlo[aw(lr, kk + 4)];
        Alo[3] = sAlo[aw(lr + 8, kk + 4)];
#pragma unroll
        for (int nt = 0; nt < 16; nt++) {
            uint4 B = sW[(ks * 16 + nt) * 32 + lane];
            mma_bf16(D1[nt], Ahi, B.x, B.y);   // hi*hi
            mma_bf16(D1[nt], Ahi, B.z, B.w);   // hi*lo
            mma_bf16(D1[nt], Alo, B.x, B.y);   // lo*hi
        }
    }
    __syncthreads();
    // Swap weights to W2
#pragma unroll
    for (int i = tid; i < 4096; i += 128) sW[i] = g_Wf2[i];
    __syncthreads();

    // Per-thread row/node bookkeeping (C-frag rows: lane>>2 and lane>>2+8)
    int n0 = nb + w * 16 + (lane >> 2);
    int n1 = n0 + 8;
    int b0 = (n0 < N) ? __ldg(x + n0) * 4 : 0;
    int b1 = (n1 < N) ? __ldg(x + n1) * 4 : 0;
    int cc = (lane & 3) * 2;

    // Attr loop: barrier-free. h built in registers from D1 per k-slice.
    for (int a = 0; a < 4; a++) {
        const float* bp0 = g_bias + (size_t)(b0 + a) * 128;
        const float* bp1 = g_bias + (size_t)(b1 + a) * 128;

        float D2[16][4];
#pragma unroll
        for (int nt = 0; nt < 16; nt++)
#pragma unroll
            for (int q = 0; q < 4; q++) D2[nt][q] = 0.f;

#pragma unroll
        for (int ks = 0; ks < 8; ks++) {
            int c0 = 16 * ks + cc;
            int c1 = c0 + 8;
            float2 q00 = *(const float2*)(bp0 + c0);
            float2 q10 = *(const float2*)(bp1 + c0);
            float2 q01 = *(const float2*)(bp0 + c1);
            float2 q11 = *(const float2*)(bp1 + c1);
            uint32_t Ahi[4], Alo[4];
            split2(fmaxf(D1[2 * ks][0] + q00.x, 0.f),
                   fmaxf(D1[2 * ks][1] + q00.y, 0.f), Ahi[0], Alo[0]);
            split2(fmaxf(D1[2 * ks][2] + q10.x, 0.f),
                   fmaxf(D1[2 * ks][3] + q10.y, 0.f), Ahi[1], Alo[1]);
            split2(fmaxf(D1[2 * ks + 1][0] + q01.x, 0.f),
                   fmaxf(D1[2 * ks + 1][1] + q01.y, 0.f), Ahi[2], Alo[2]);
            split2(fmaxf(D1[2 * ks + 1][2] + q11.x, 0.f),
                   fmaxf(D1[2 * ks + 1][3] + q11.y, 0.f), Ahi[3], Alo[3]);
#pragma unroll
            for (int nt = 0; nt < 16; nt++) {
                uint4 B = sW[(ks * 16 + nt) * 32 + lane];
                mma_bf16(D2[nt], Ahi, B.x, B.y);
                mma_bf16(D2[nt], Ahi, B.z, B.w);
                mma_bf16(D2[nt], Alo, B.x, B.y);
            }
        }

        // Epilogue: msg = relu(D2 + bu2) -> msgOut (fp16)
        __half* mp0 = msgOut + ((size_t)n0 * 4 + a) * 128;
        __half* mp1 = msgOut + ((size_t)n1 * 4 + a) * 128;
#pragma unroll
        for (int nt = 0; nt < 16; nt++) {
            float2 b2 = *(const float2*)(bu2 + nt * 8 + cc);
            if (n0 < N) {
                __half2 o = __floats2half2_rn(fmaxf(D2[nt][0] + b2.x, 0.f),
                                              fmaxf(D2[nt][1] + b2.y, 0.f));
                *(__half2*)(mp0 + nt * 8 + cc) = o;
            }
            if (n1 < N) {
                __half2 o = __floats2half2_rn(fmaxf(D2[nt][2] + b2.x, 0.f),
                                              fmaxf(D2[nt][3] + b2.y, 0.f));
                *(__half2*)(mp1 + nt * 8 + cc) = o;
            }
        }
    }
}

// ---------------------------------------------------------------------------
__global__ void readout_kernel(const float* __restrict__ Wr1,
                               const float* __restrict__ br1,
                               const float* __restrict__ Wr2,
                               const float* __restrict__ br2,
                               float* __restrict__ out) {
    int m = blockIdx.x;
    int tid = threadIdx.x;  // 256
    __shared__ float sMol[128];
    __shared__ float sRed[8];
    if (tid < 128) sMol[tid] = g_mol[m * 128 + tid];
    __syncthreads();

    float part = 0.f;
#pragma unroll
    for (int jj = 0; jj < 2; jj++) {
        int j = tid + jj * 256;
        float h = br1[j];
#pragma unroll 8
        for (int k = 0; k < 128; k++)
            h = fmaf(sMol[k], Wr1[k * 512 + j], h);
        h = fmaxf(h, 0.f);
        part = fmaf(h, Wr2[j], part);
    }
#pragma unroll
    for (int off = 16; off; off >>= 1)
        part += __shfl_down_sync(0xffffffffu, part, off);
    if ((tid & 31) == 0) sRed[tid >> 5] = part;
    __syncthreads();
    if (tid == 0) {
        float s = br2[0];
#pragma unroll
        for (int i = 0; i < 8; i++) s += sRed[i];
        out[m] = s;
    }
}

// ---------------------------------------------------------------------------
extern "C" void kernel_launch(void* const* d_in, const int* in_sizes, int n_in,
                              void* d_out, int out_size) {
    const int*   x          = (const int*)d_in[0];
    const int*   eattr      = (const int*)d_in[1];
    const int*   eidx       = (const int*)d_in[2];
    const int*   batch      = (const int*)d_in[3];
    const float* atom_table = (const float*)d_in[4];
    const float* bond_table = (const float*)d_in[5];
    const float* Wi         = (const float*)d_in[6];
    const float* bi         = (const float*)d_in[7];
    const float* Wu1        = (const float*)d_in[8];
    const float* bu1        = (const float*)d_in[9];
    const float* Wu2        = (const float*)d_in[10];
    const float* bu2        = (const float*)d_in[11];
    const float* Wr1        = (const float*)d_in[12];
    const float* br1        = (const float*)d_in[13];
    const float* Wr2        = (const float*)d_in[14];
    const float* br2        = (const float*)d_in[15];
    float* out = (float*)d_out;

    int N = in_sizes[0];
    int E = in_sizes[1];
    int M = out_size;
    const int* src = eidx;
    const int* dst = eidx + E;

    cudaFuncSetAttribute(fused_update_kernel,
                         cudaFuncAttributeMaxDynamicSharedMemorySize, SM_UPD);

    int scanB = (N + 255) / 256;

    // Tables (+hist zero) + weight frag images (+mol zero) + CSR build
    table_kernel<<<NTAB, 128>>>(atom_table, bond_table, Wi, bi, Wu1, bu1, N);
    prep_wfrag_kernel<<<16, 256>>>(Wu1 + 192 * 128, Wu2);
    csr_count_kernel<<<512, 256>>>(dst, E);
    csr_scan1_kernel<<<scanB, 256>>>(N);
    csr_scan2_kernel<<<1, 256>>>(scanB, N);
    csr_scan3_kernel<<<scanB, 256>>>(N);
    csr_fill_kernel<<<512, 256>>>(src, dst, eattr, x, E);

    // 4 fused gather+update passes, ping-pong msg buffers:
    // p0: init -> T0, p1: T0 -> T1, p2: T1 -> T0, p3: T0 -> T1
    for (int p = 0; p < 4; p++)
        fused_update_kernel<<<(N + 63) / 64, 128, SM_UPD>>>(p == 0, p & 1,
                                                            x, bu2, N);

    // Final segment-sum of messages (in T1) pooled straight into molecules
    gather_mol_kernel<<<2048, 256>>>(batch, N);
    readout_kernel<<<M, 256>>>(Wr1, br1, Wr2, br2, out);
}

// round 17
// speedup vs baseline: 1.4853x; 1.4853x over previous
#include <cuda_runtime.h>
#include <cuda_bf16.h>
#include <cuda_fp16.h>
#include <cstdint>

// ---------------------------------------------------------------------------
// BasicDMPNN on GB300 — round 17: r15 base + MLP-4 gather inner loop.
//   * fusion conclusively abandoned (0-for-4)
//   * gather: 4 message rows in flight per warp (was 2) -> L2-bw-bound
//   * fp16 message transport, bf16x3 mma.sync update (at HMMA roofline),
//     parallel CSR scan, piggybacked zero fills
// ---------------------------------------------------------------------------

#define NMAX 50000
#define EMAX 800000
#define MMAX 2000
#define NTAB 476

__device__ __align__(16) float g_bias[NTAB * 128];      // ab@Wu1[:192]+bu1
__device__ __align__(16) __half g_msgInit[NTAB * 128];  // relu(ab@Wi+bi), fp16
__device__ __align__(16) float g_agg[NMAX * 128];
__device__ __align__(16) __half g_msgTable[NMAX * 4 * 128];
__device__ __align__(16) float g_mol[MMAX * 128];
__device__ __align__(16) uint4 g_Wf1[4096];             // Wu1agg frag image (hi/lo)
__device__ __align__(16) uint4 g_Wf2[4096];             // Wu2 frag image (hi/lo)

// CSR scratch
__device__ int g_hist[NMAX];
__device__ int g_rowStart[NMAX + 1];
__device__ int g_cursor[NMAX];
__device__ int g_blockSum[256];
__device__ int g_blockOff[256];
__device__ int g_row0[EMAX];   // x[src]*4+attr
__device__ int g_rowU[EMAX];   // src*4+attr

// ---------------------------------------------------------------------------
__device__ __forceinline__ uint32_t pack_bf16x2(float e0, float e1) {
    __nv_bfloat162 p = __floats2bfloat162_rn(e0, e1);
    return *reinterpret_cast<uint32_t*>(&p);
}
__device__ __forceinline__ void split2(float e0, float e1,
                                       uint32_t& hi, uint32_t& lo) {
    float h0 = __bfloat162float(__float2bfloat16(e0));
    float h1 = __bfloat162float(__float2bfloat16(e1));
    hi = pack_bf16x2(h0, h1);
    lo = pack_bf16x2(e0 - h0, e1 - h1);
}
__device__ __forceinline__ void mma_bf16(float d[4], const uint32_t a[4],
                                         uint32_t b0, uint32_t b1) {
    asm volatile(
        "mma.sync.aligned.m16n8k16.row.col.f32.bf16.bf16.f32 "
        "{%0,%1,%2,%3}, {%4,%5,%6,%7}, {%8,%9}, {%0,%1,%2,%3};"
        : "+f"(d[0]), "+f"(d[1]), "+f"(d[2]), "+f"(d[3])
        : "r"(a[0]), "r"(a[1]), "r"(a[2]), "r"(a[3]), "r"(b0), "r"(b1));
}
// swizzled index into a 16-row x 64-word per-warp staging tile
__device__ __forceinline__ int aw(int row, int kk) {
    return row * 64 + (kk ^ ((row & 7) << 2));
}
__device__ __forceinline__ void acc_u2(float4& acc, uint2 u) {
    __half2 p0 = *reinterpret_cast<__half2*>(&u.x);
    __half2 p1 = *reinterpret_cast<__half2*>(&u.y);
    float2 f0 = __half22float2(p0);
    float2 f1 = __half22float2(p1);
    acc.x += f0.x; acc.y += f0.y; acc.z += f1.x; acc.w += f1.y;
}

// Block-wide (256 threads) exclusive scan of one int per thread.
__device__ __forceinline__ int block_scan_ex(int v, int tid) {
    int lane = tid & 31;
    int wid = tid >> 5;
    int inc = v;
#pragma unroll
    for (int o = 1; o < 32; o <<= 1) {
        int t = __shfl_up_sync(0xffffffffu, inc, o);
        if (lane >= o) inc += t;
    }
    __shared__ int wsum[8], woff[8];
    if (lane == 31) wsum[wid] = inc;
    __syncthreads();
    if (tid == 0) {
        int run = 0;
#pragma unroll
        for (int k = 0; k < 8; k++) { woff[k] = run; run += wsum[k]; }
    }
    __syncthreads();
    return woff[wid] + inc - v;
}

// ---------------------------------------------------------------------------
// CSR build: count -> 3-phase parallel scan -> fill
// ---------------------------------------------------------------------------
__global__ void csr_count_kernel(const int* __restrict__ dst, int E) {
    for (int e = blockIdx.x * blockDim.x + threadIdx.x; e < E;
         e += gridDim.x * blockDim.x)
        atomicAdd(&g_hist[dst[e]], 1);
}
__global__ void csr_scan1_kernel(int N) {
    int i = blockIdx.x * 256 + threadIdx.x;
    int v = (i < N) ? g_hist[i] : 0;
    int ex = block_scan_ex(v, threadIdx.x);
    if (i < N) g_rowStart[i] = ex;
    if (threadIdx.x == 255) g_blockSum[blockIdx.x] = ex + v;
}
__global__ void csr_scan2_kernel(int B, int N) {
    int tid = threadIdx.x;
    int v = (tid < B) ? g_blockSum[tid] : 0;
    int ex = block_scan_ex(v, tid);
    if (tid < B) g_blockOff[tid] = ex;
    if (tid == B - 1) g_rowStart[N] = ex + v;
}
__global__ void csr_scan3_kernel(int N) {
    int i = blockIdx.x * 256 + threadIdx.x;
    if (i < N) {
        int val = g_rowStart[i] + g_blockOff[blockIdx.x];
        g_rowStart[i] = val;
        g_cursor[i] = val;
    }
}
__global__ void csr_fill_kernel(const int* __restrict__ src,
                                const int* __restrict__ dst,
                                const int* __restrict__ attr,
                                const int* __restrict__ x, int E) {
    for (int e = blockIdx.x * blockDim.x + threadIdx.x; e < E;
         e += gridDim.x * blockDim.x) {
        int d = dst[e];
        int s = src[e];
        int a = attr[e];
        int pos = atomicAdd(&g_cursor[d], 1);
        g_rowU[pos] = s * 4 + a;
        g_row0[pos] = x[s] * 4 + a;
    }
}

// ---------------------------------------------------------------------------
// Aggregation: warp per node, fp16 rows -> fp32 register reduce, MLP-4.
// mode 0: rows=g_row0, table=g_msgInit, out -> g_agg
// mode 1: rows=g_rowU, table=g_msgTable, out -> g_agg
// mode 2: rows=g_rowU, table=g_msgTable, out -> red.add g_mol[batch[n]]
__global__ void gather_agg_kernel(int mode, const int* __restrict__ batch, int N) {
    const int* __restrict__ rowids = (mode == 0) ? g_row0 : g_rowU;
    const __half* __restrict__ table = (mode == 0) ? g_msgInit : g_msgTable;
    int lane = threadIdx.x & 31;
    int w = (blockIdx.x * blockDim.x + threadIdx.x) >> 5;
    int nw = (gridDim.x * blockDim.x) >> 5;
    for (int n = w; n < N; n += nw) {
        int s0 = g_rowStart[n];
        int s1 = g_rowStart[n + 1];
        float4 acc = make_float4(0.f, 0.f, 0.f, 0.f);
        int j = s0;
        for (; j + 4 <= s1; j += 4) {
            int r0 = __ldg(rowids + j);
            int r1 = __ldg(rowids + j + 1);
            int r2 = __ldg(rowids + j + 2);
            int r3 = __ldg(rowids + j + 3);
            uint2 u0 = ((const uint2*)(table + (size_t)r0 * 128))[lane];
            uint2 u1 = ((const uint2*)(table + (size_t)r1 * 128))[lane];
            uint2 u2 = ((const uint2*)(table + (size_t)r2 * 128))[lane];
            uint2 u3 = ((const uint2*)(table + (size_t)r3 * 128))[lane];
            acc_u2(acc, u0);
            acc_u2(acc, u1);
            acc_u2(acc, u2);
            acc_u2(acc, u3);
        }
        if (j + 2 <= s1) {
            int r0 = __ldg(rowids + j);
            int r1 = __ldg(rowids + j + 1);
            uint2 u0 = ((const uint2*)(table + (size_t)r0 * 128))[lane];
            uint2 u1 = ((const uint2*)(table + (size_t)r1 * 128))[lane];
            acc_u2(acc, u0);
            acc_u2(acc, u1);
            j += 2;
        }
        if (j < s1) {
            int r0 = __ldg(rowids + j);
            uint2 u0 = ((const uint2*)(table + (size_t)r0 * 128))[lane];
            acc_u2(acc, u0);
        }
        if (mode == 2) {
            float* outp = g_mol + (size_t)__ldg(batch + n) * 128 + lane * 4;
            asm volatile("red.global.add.v4.f32 [%0], {%1,%2,%3,%4};"
                         :: "l"(outp), "f"(acc.x), "f"(acc.y), "f"(acc.z), "f"(acc.w)
                         : "memory");
        } else {
            ((float4*)(g_agg + (size_t)n * 128))[lane] = acc;
        }
    }
}

// ---------------------------------------------------------------------------
// Build the two 476x128 tables (fp32 math; msgInit stored fp16).
// Piggyback: zero g_hist.
__global__ void table_kernel(const float* __restrict__ atom_table,
                             const float* __restrict__ bond_table,
                             const float* __restrict__ Wi,
                             const float* __restrict__ bi,
                             const float* __restrict__ Wu1,
                             const float* __restrict__ bu1, int N) {
    int t = blockIdx.x >> 2;
    int a = blockIdx.x & 3;
    int j = threadIdx.x;

    for (int i = blockIdx.x * 128 + j; i < N; i += NTAB * 128) g_hist[i] = 0;

    __shared__ float sAtom[128];
    __shared__ float sBond[64];
    sAtom[j] = atom_table[t * 128 + j];
    if (j < 64) sBond[j] = bond_table[a * 64 + j];
    __syncthreads();

    float accI = bi[j];
    float accB = bu1[j];
#pragma unroll 8
    for (int k = 0; k < 128; k++) {
        float av = sAtom[k];
        accI = fmaf(av, Wi[k * 128 + j], accI);
        accB = fmaf(av, Wu1[k * 128 + j], accB);
    }
#pragma unroll 8
    for (int k = 0; k < 64; k++) {
        float bv = sBond[k];
        accI = fmaf(bv, Wi[(128 + k) * 128 + j], accI);
        accB = fmaf(bv, Wu1[(128 + k) * 128 + j], accB);
    }
    g_msgInit[blockIdx.x * 128 + j] = __float2half_rn(fmaxf(accI, 0.f));
    g_bias[blockIdx.x * 128 + j] = accB;
}

// ---------------------------------------------------------------------------
// Pack W (k-major [128,128]) into fragment-ordered bf16 hi/lo images.
// Piggyback: zero g_mol.
__global__ void prep_wfrag_kernel(const float* __restrict__ W1,
                                  const float* __restrict__ W2) {
    int i = blockIdx.x * blockDim.x + threadIdx.x;
    {
        float4 z = make_float4(0.f, 0.f, 0.f, 0.f);
        float4* p = (float4*)g_mol;
        for (int q = i; q < MMAX * 32; q += 4096) p[q] = z;
    }
    if (i >= 4096) return;
    int lane = i & 31;
    int ntile = (i >> 5) & 15;
    int ks = i >> 9;
    int k0 = ks * 16 + (lane & 3) * 2;
    int n = ntile * 8 + (lane >> 2);

    const float* Ws[2] = {W1, W2};
    uint4* imgs[2] = {g_Wf1, g_Wf2};
#pragma unroll
    for (int m = 0; m < 2; m++) {
        const float* W = Ws[m];
        uint4 v;
        split2(W[k0 * 128 + n], W[(k0 + 1) * 128 + n], v.x, v.z);
        split2(W[(k0 + 8) * 128 + n], W[(k0 + 9) * 128 + n], v.y, v.w);
        imgs[m][i] = v;
    }
}

// ---------------------------------------------------------------------------
// Update pass: 64 nodes/block, 128 threads (4 warps x 16 nodes), 2 blocks/SM.
// smem: sAhi 16KB + sAlo 16KB (per-warp 16x64 staging) + sW 64KB = 96KB.
#define SM_UPD (16384 + 16384 + 65536)

__global__ void __launch_bounds__(128, 2)
update_mma_kernel(const int* __restrict__ x, const float* __restrict__ bu2, int N) {
    extern __shared__ uint32_t smem[];
    uint4* sW = (uint4*)(smem + 8192);     // 4096 uint4 (64KB), W1 then W2

    int tid = threadIdx.x;
    int lane = tid & 31;
    int w = tid >> 5;                      // warp 0..3, owns rows w*16..+15
    int nb = blockIdx.x * 64;
    uint32_t* sAhi = smem + w * 1024;      // warp-private 16x64 staging
    uint32_t* sAlo = smem + 4096 + w * 1024;

    // Phase 0: W1 -> smem (cooperative) + per-warp A staging from g_agg
#pragma unroll
    for (int i = tid; i < 4096; i += 128) sW[i] = g_Wf1[i];
#pragma unroll
    for (int r = 0; r < 16; r++) {
        int n = nb + w * 16 + r;
        float4 v = (n < N) ? ((const float4*)(g_agg + (size_t)n * 128))[lane]
                           : make_float4(0.f, 0.f, 0.f, 0.f);
        uint32_t h0, l0, h1, l1;
        split2(v.x, v.y, h0, l0);
        split2(v.z, v.w, h1, l1);
        int p = aw(r, 2 * lane);
        sAhi[p] = h0; sAhi[p + 1] = h1;
        sAlo[p] = l0; sAlo[p + 1] = l1;
    }
    __syncthreads();

    // GEMM1: D1 = agg @ Wu1agg — warp computes its 16 rows x ALL 128 cols.
    float D1[16][4];
#pragma unroll
    for (int nt = 0; nt < 16; nt++)
#pragma unroll
        for (int q = 0; q < 4; q++) D1[nt][q] = 0.f;

#pragma unroll
    for (int ks = 0; ks < 8; ks++) {
        int lr = lane >> 2;
        int kk = ks * 8 + (lane & 3);
        uint32_t Ahi[4], Alo[4];
        Ahi[0] = sAhi[aw(lr, kk)];
        Ahi[1] = sAhi[aw(lr + 8, kk)];
        Ahi[2] = sAhi[aw(lr, kk + 4)];
        Ahi[3] = sAhi[aw(lr + 8, kk + 4)];
        Alo[0] = sAlo[aw(lr, kk)];
        Alo[1] = sAlo[aw(lr + 8, kk)];
        Alo[2] = sAlo[aw(lr, kk + 4)];
        Alo[3] = sAlo[aw(lr + 8, kk + 4)];
#pragma unroll
        for (int nt = 0; nt < 16; nt++) {
            uint4 B = sW[(ks * 16 + nt) * 32 + lane];
            mma_bf16(D1[nt], Ahi, B.x, B.y);   // hi*hi
            mma_bf16(D1[nt], Ahi, B.z, B.w);   // hi*lo
            mma_bf16(D1[nt], Alo, B.x, B.y);   // lo*hi
        }
    }
    __syncthreads();
    // Swap weights to W2
#pragma unroll
    for (int i = tid; i < 4096; i += 128) sW[i] = g_Wf2[i];
    __syncthreads();

    // Per-thread row/node bookkeeping (C-frag rows: lane>>2 and lane>>2+8)
    int n0 = nb + w * 16 + (lane >> 2);
    int n1 = n0 + 8;
    int b0 = (n0 < N) ? __ldg(x + n0) * 4 : 0;
    int b1 = (n1 < N) ? __ldg(x + n1) * 4 : 0;
    int cc = (lane & 3) * 2;

    // Attr loop: barrier-free. h built in registers from D1 per k-slice.
    for (int a = 0; a < 4; a++) {
        const float* bp0 = g_bias + (size_t)(b0 + a) * 128;
        const float* bp1 = g_bias + (size_t)(b1 + a) * 128;

        float D2[16][4];
#pragma unroll
        for (int nt = 0; nt < 16; nt++)
#pragma unroll
            for (int q = 0; q < 4; q++) D2[nt][q] = 0.f;

#pragma unroll
        for (int ks = 0; ks < 8; ks++) {
            int c0 = 16 * ks + cc;
            int c1 = c0 + 8;
            float2 q00 = *(const float2*)(bp0 + c0);
            float2 q10 = *(const float2*)(bp1 + c0);
            float2 q01 = *(const float2*)(bp0 + c1);
            float2 q11 = *(const float2*)(bp1 + c1);
            uint32_t Ahi[4], Alo[4];
            split2(fmaxf(D1[2 * ks][0] + q00.x, 0.f),
                   fmaxf(D1[2 * ks][1] + q00.y, 0.f), Ahi[0], Alo[0]);
            split2(fmaxf(D1[2 * ks][2] + q10.x, 0.f),
                   fmaxf(D1[2 * ks][3] + q10.y, 0.f), Ahi[1], Alo[1]);
            split2(fmaxf(D1[2 * ks + 1][0] + q01.x, 0.f),
                   fmaxf(D1[2 * ks + 1][1] + q01.y, 0.f), Ahi[2], Alo[2]);
            split2(fmaxf(D1[2 * ks + 1][2] + q11.x, 0.f),
                   fmaxf(D1[2 * ks + 1][3] + q11.y, 0.f), Ahi[3], Alo[3]);
#pragma unroll
            for (int nt = 0; nt < 16; nt++) {
                uint4 B = sW[(ks * 16 + nt) * 32 + lane];
                mma_bf16(D2[nt], Ahi, B.x, B.y);
                mma_bf16(D2[nt], Ahi, B.z, B.w);
                mma_bf16(D2[nt], Alo, B.x, B.y);
            }
        }

        // Epilogue: msg = relu(D2 + bu2) -> g_msgTable (fp16)
        __half* mp0 = g_msgTable + ((size_t)n0 * 4 + a) * 128;
        __half* mp1 = g_msgTable + ((size_t)n1 * 4 + a) * 128;
#pragma unroll
        for (int nt = 0; nt < 16; nt++) {
            float2 b2 = *(const float2*)(bu2 + nt * 8 + cc);
            if (n0 < N) {
                __half2 o = __floats2half2_rn(fmaxf(D2[nt][0] + b2.x, 0.f),
                                              fmaxf(D2[nt][1] + b2.y, 0.f));
                *(__half2*)(mp0 + nt * 8 + cc) = o;
            }
            if (n1 < N) {
                __half2 o = __floats2half2_rn(fmaxf(D2[nt][2] + b2.x, 0.f),
                                              fmaxf(D2[nt][3] + b2.y, 0.f));
                *(__half2*)(mp1 + nt * 8 + cc) = o;
            }
        }
    }
}

// ---------------------------------------------------------------------------
__global__ void readout_kernel(const float* __restrict__ Wr1,
                               const float* __restrict__ br1,
                               const float* __restrict__ Wr2,
                               const float* __restrict__ br2,
                               float* __restrict__ out) {
    int m = blockIdx.x;
    int tid = threadIdx.x;  // 256
    __shared__ float sMol[128];
    __shared__ float sRed[8];
    if (tid < 128) sMol[tid] = g_mol[m * 128 + tid];
    __syncthreads();

    float part = 0.f;
#pragma unroll
    for (int jj = 0; jj < 2; jj++) {
        int j = tid + jj * 256;
        float h = br1[j];
#pragma unroll 8
        for (int k = 0; k < 128; k++)
            h = fmaf(sMol[k], Wr1[k * 512 + j], h);
        h = fmaxf(h, 0.f);
        part = fmaf(h, Wr2[j], part);
    }
#pragma unroll
    for (int off = 16; off; off >>= 1)
        part += __shfl_down_sync(0xffffffffu, part, off);
    if ((tid & 31) == 0) sRed[tid >> 5] = part;
    __syncthreads();
    if (tid == 0) {
        float s = br2[0];
#pragma unroll
        for (int i = 0; i < 8; i++) s += sRed[i];
        out[m] = s;
    }
}

// ---------------------------------------------------------------------------
extern "C" void kernel_launch(void* const* d_in, const int* in_sizes, int n_in,
                              void* d_out, int out_size) {
    const int*   x          = (const int*)d_in[0];
    const int*   eattr      = (const int*)d_in[1];
    const int*   eidx       = (const int*)d_in[2];
    const int*   batch      = (const int*)d_in[3];
    const float* atom_table = (const float*)d_in[4];
    const float* bond_table = (const float*)d_in[5];
    const float* Wi         = (const float*)d_in[6];
    const float* bi         = (const float*)d_in[7];
    const float* Wu1        = (const float*)d_in[8];
    const float* bu1        = (const float*)d_in[9];
    const float* Wu2        = (const float*)d_in[10];
    const float* bu2        = (const float*)d_in[11];
    const float* Wr1        = (const float*)d_in[12];
    const float* br1        = (const float*)d_in[13];
    const float* Wr2        = (const float*)d_in[14];
    const float* br2        = (const float*)d_in[15];
    float* out = (float*)d_out;

    int N = in_sizes[0];
    int E = in_sizes[1];
    int M = out_size;
    const int* src = eidx;
    const int* dst = eidx + E;

    cudaFuncSetAttribute(update_mma_kernel,
                         cudaFuncAttributeMaxDynamicSharedMemorySize, SM_UPD);

    int scanB = (N + 255) / 256;

    // Tables (+hist zero) + weight frag images (+mol zero) + CSR build
    table_kernel<<<NTAB, 128>>>(atom_table, bond_table, Wi, bi, Wu1, bu1, N);
    prep_wfrag_kernel<<<16, 256>>>(Wu1 + 192 * 128, Wu2);
    csr_count_kernel<<<512, 256>>>(dst, E);
    csr_scan1_kernel<<<scanB, 256>>>(N);
    csr_scan2_kernel<<<1, 256>>>(scanB, N);
    csr_scan3_kernel<<<scanB, 256>>>(N);
    csr_fill_kernel<<<512, 256>>>(src, dst, eattr, x, E);

    // Initial message aggregation (476-row fp16 table, cache-resident)
    gather_agg_kernel<<<3072, 256>>>(0, batch, N);

    for (int p = 0; p < 4; p++) {
        update_mma_kernel<<<(N + 63) / 64, 128, SM_UPD>>>(x, bu2, N);
        gather_agg_kernel<<<3072, 256>>>((p < 3) ? 1 : 2, batch, N);
    }

    readout_kernel<<<M, 256>>>(Wr1, br1, Wr2, br2, out);
}